// round 16
// baseline (speedup 1.0000x reference)
#include <cuda_runtime.h>
#include <cuda_bf16.h>
#include <cuda_fp16.h>
#include <cstdint>

#define LSEQ 1024
#define DM   1024
#define BATCH 8
#define NH   16
#define DK   64
#define BHN  (BATCH*NH)     // 128
#define NREL 33
#define DI   4096
#define ROWS (BATCH*LSEQ)   // 8192

// ---------------- scratch (static device arrays; no allocation) ----------------
__device__ float g_tmp[ROWS*DM];
__device__ float g_ln1[ROWS*DM];
__device__ float g_t2[ROWS*DM];
__device__ float g_bqkv[3*DM];
// fp16 buffers
__device__ __half g_Ah[(size_t)ROWS*DI];         // stacked QKV inputs / h1 (fp16)
__device__ __half g_Xh[ROWS*DM];                 // current activation (fp16)
__device__ __half g_Wh[(size_t)DM*DI];           // weights (fp16, stacked for QKV)
__device__ __half g_Qh[ROWS*DM];
__device__ __half g_Kh[ROWS*DM];
__device__ __half g_Vth[(size_t)BHN*DK*LSEQ];    // [bh][d][k] fp16
__device__ __half g_RKh[48*DK];                  // rel_k fp16, padded to 48 rows

// ---------------- helpers ----------------
__device__ __forceinline__ uint32_t smem_u32(const void* p) {
    uint32_t a;
    asm("{ .reg .u64 t; cvta.to.shared.u64 t, %1; cvt.u32.u64 %0, t; }" : "=r"(a) : "l"(p));
    return a;
}
__device__ __forceinline__ void cp_async16(uint32_t saddr, const void* gaddr) {
    asm volatile("cp.async.cg.shared.global [%0], [%1], 16;" :: "r"(saddr), "l"(gaddr));
}
__device__ __forceinline__ void cp_commit() {
    asm volatile("cp.async.commit_group;" ::: "memory");
}
__device__ __forceinline__ void cp_wait2() {
    asm volatile("cp.async.wait_group 2;" ::: "memory");
}
__device__ __forceinline__ void cp_wait1() {
    asm volatile("cp.async.wait_group 1;" ::: "memory");
}
__device__ __forceinline__ void cp_wait0() {
    asm volatile("cp.async.wait_group 0;" ::: "memory");
}
__device__ __forceinline__ void cp_async_wait_all() {
    asm volatile("cp.async.commit_group;\ncp.async.wait_group 0;" ::: "memory");
}
__device__ __forceinline__ void ldmx4(uint32_t* r, uint32_t addr) {
    asm volatile("ldmatrix.sync.aligned.m8n8.x4.shared.b16 {%0,%1,%2,%3}, [%4];"
        : "=r"(r[0]), "=r"(r[1]), "=r"(r[2]), "=r"(r[3]) : "r"(addr));
}
__device__ __forceinline__ void mma_f16(float* c, const uint32_t* a, uint32_t b0, uint32_t b1) {
    asm volatile(
        "mma.sync.aligned.m16n8k16.row.col.f32.f16.f16.f32 "
        "{%0,%1,%2,%3}, {%4,%5,%6,%7}, {%8,%9}, {%0,%1,%2,%3};"
        : "+f"(c[0]), "+f"(c[1]), "+f"(c[2]), "+f"(c[3])
        : "r"(a[0]), "r"(a[1]), "r"(a[2]), "r"(a[3]), "r"(b0), "r"(b1));
}
__device__ __forceinline__ uint32_t pkh2(__half lo, __half hi) {
    __half2 t(lo, hi);
    return *(uint32_t*)&t;
}

// ---------------- conversion kernels ----------------
// q/k/v fp32 -> stacked fp16 (one launch, grid.y = which tensor)
__global__ void conv3_h(const float* __restrict__ q, const float* __restrict__ k,
                        const float* __restrict__ v, __half* __restrict__ H) {
    int z = blockIdx.y;
    const float* X = (z == 0) ? q : ((z == 1) ? k : v);
    int i = blockIdx.x * blockDim.x + threadIdx.x;
    float4 val = ((const float4*)X)[i];
    __half h[4] = {__float2half_rn(val.x), __float2half_rn(val.y),
                   __float2half_rn(val.z), __float2half_rn(val.w)};
    *(uint2*)(H + (size_t)z * ROWS * DM + (size_t)i * 4) = *(uint2*)h;
}

// ---- fast transpose: W[K,N] -> fp16 T [N,K], 64x64 tiles, vectorized ----
__device__ __forceinline__ void transT64(const float* __restrict__ W, __half* __restrict__ hT,
                                         int K, int N, int n0, int k0) {
    __shared__ float t[64][65];
    int tid = threadIdx.x;
#pragma unroll
    for (int i = 0; i < 4; i++) {
        int f = tid + i * 256;               // 1024 float4 = 64 rows x 16 segs
        int r = f >> 4, c4 = f & 15;
        float4 v = *(const float4*)(W + (size_t)(k0 + r) * N + n0 + c4 * 4);
        t[r][c4 * 4 + 0] = v.x; t[r][c4 * 4 + 1] = v.y;
        t[r][c4 * 4 + 2] = v.z; t[r][c4 * 4 + 3] = v.w;
    }
    __syncthreads();
#pragma unroll
    for (int i = 0; i < 2; i++) {
        int f = tid + i * 256;               // 512 = 64 n-rows x 8 ksegs
        int n = f >> 3, s = f & 7;
        __half h[8];
#pragma unroll
        for (int j = 0; j < 8; j++) h[j] = __float2half_rn(t[s * 8 + j][n]);
        *(uint4*)(hT + (size_t)(n0 + n) * K + k0 + s * 8) = *(uint4*)h;
    }
}

__global__ void conv_T_h(const float* __restrict__ W, __half* __restrict__ hT, int K, int N) {
    transT64(W, hT, K, N, blockIdx.x * 64, blockIdx.y * 64);
}

// wq/wk/wv -> stacked fp16 T (one launch, grid.z selects)
__global__ void convT3_h(const float* __restrict__ wq, const float* __restrict__ wk,
                         const float* __restrict__ wv, __half* __restrict__ hT) {
    int z = blockIdx.z;
    const float* W = (z == 0) ? wq : ((z == 1) ? wk : wv);
    transT64(W, hT + (size_t)z * DM * DM, DM, DM, blockIdx.x * 64, blockIdx.y * 64);
}

// rel_k [33,64] -> padded [48,64] fp16
__global__ void relk_h(const float* __restrict__ rel_k) {
    int i = blockIdx.x * 256 + threadIdx.x;   // 0..3071
    int r = i >> 6;
    float x = (r < NREL) ? rel_k[i] : 0.f;
    g_RKh[i] = __float2half_rn(x);
}

__global__ void bias_concat(const float* __restrict__ b0, const float* __restrict__ b1,
                            const float* __restrict__ b2) {
    int i = blockIdx.x * 256 + threadIdx.x;   // 0..3071
    g_bqkv[i] = (i < DM) ? b0[i] : ((i < 2 * DM) ? b1[i - DM] : b2[i - 2 * DM]);
}

#define SPAD 40
#define GSTAGE_S 20480          // 2 arrays x 10240
#define GEMM_S_SMEM (3 * GSTAGE_S)

// ---------------- fp16 single-pass QKV GEMM (stacked segments, 3-stage pipe) ----------------
// Epilogue: seg0->g_Qh fp16, seg1->g_Kh fp16, seg2->transposed fp16 g_Vth.
__global__ __launch_bounds__(256, 2) void gemm_qkv_h(
    const __half* __restrict__ Ah, const __half* __restrict__ Bh,
    const float* __restrict__ bias)
{
    extern __shared__ char gsm[];
    const uint32_t base = smem_u32(gsm);

    const int tid = threadIdx.x;
    const int wid = tid >> 5, lane = tid & 31;
    const int wm = wid >> 2, wn = wid & 3;
    const int bm = blockIdx.y * 128, bn = blockIdx.x * 128;

    const int seg = bn >> 10;
    const int bnl = bn & (DM - 1);
    Ah += (size_t)seg * ROWS * DM;
    Bh += (size_t)seg * DM * DM;

    float c[4][4][4];
#pragma unroll
    for (int mt = 0; mt < 4; mt++)
#pragma unroll
        for (int nt = 0; nt < 4; nt++)
#pragma unroll
            for (int r = 0; r < 4; r++) c[mt][nt][r] = 0.f;

    const int a_m_base = wm * 64 + (lane & 7) + 8 * ((lane >> 3) & 1);
    const int a_kk = 8 * (lane >> 4);
    const int b_n_base = wn * 32 + (lane & 7) + 8 * (lane >> 4);
    const int b_kk = 8 * ((lane >> 3) & 1);

    const int ktiles = DM >> 5;

    auto load_tile = [&](int t, int s) {
        const int kbase = t * 32;
        const uint32_t sb = base + s * GSTAGE_S;
#pragma unroll
        for (int i = 0; i < 2; i++) {
            int f = tid + i * 256;
            int row = f >> 2, seg2 = f & 3;
            uint32_t so = (uint32_t)(row * SPAD + seg2 * 8) * 2;
            cp_async16(sb + so, Ah + (size_t)(bm + row) * DM + kbase + seg2 * 8);
            cp_async16(sb + 10240 + so, Bh + (size_t)(bnl + row) * DM + kbase + seg2 * 8);
        }
        cp_commit();
    };

    load_tile(0, 0);
    load_tile(1, 1);
    int ls = 2, cs = 0;
    for (int t = 0; t < ktiles; t++) {
        if (t + 2 < ktiles) {
            load_tile(t + 2, ls);
            if (++ls == 3) ls = 0;
            cp_wait2();
        } else if (t + 1 < ktiles) {
            cp_wait1();
        } else {
            cp_wait0();
        }
        __syncthreads();

        const uint32_t sb = base + cs * GSTAGE_S;
        if (++cs == 3) cs = 0;
        const uint32_t aA = sb, aB = sb + 10240;
#pragma unroll
        for (int kh = 0; kh < 2; kh++) {
            const int k0 = kh * 16;
            uint32_t bh[8];
#pragma unroll
            for (int p = 0; p < 2; p++) {
                uint32_t off = (uint32_t)((b_n_base + p * 16) * SPAD + k0 + b_kk) * 2;
                ldmx4(bh + p * 4, aB + off);
            }
#pragma unroll
            for (int mt = 0; mt < 4; mt++) {
                uint32_t ah[4];
                uint32_t off = (uint32_t)((a_m_base + mt * 16) * SPAD + k0 + a_kk) * 2;
                ldmx4(ah, aA + off);
#pragma unroll
                for (int nt = 0; nt < 4; nt++)
                    mma_f16(c[mt][nt], ah, bh[nt * 2], bh[nt * 2 + 1]);
            }
        }
        __syncthreads();
    }

    const int r0 = lane >> 2, c0 = (lane & 3) * 2;
    if (seg == 2) {
        // ---- stage transposed fp16 V tile in smem, then coalesced Vt writes ----
        __half* T = (__half*)gsm;           // [128 cols][136 rows] fp16
#pragma unroll
        for (int mt = 0; mt < 4; mt++) {
            int rl = wm * 64 + mt * 16 + r0;
#pragma unroll
            for (int nt = 0; nt < 4; nt++) {
                int cl = wn * 32 + nt * 8 + c0;
                float b0v = bias[bn + cl], b1v = bias[bn + cl + 1];
                T[cl * 136 + rl]           = __float2half_rn(c[mt][nt][0] + b0v);
                T[(cl + 1) * 136 + rl]     = __float2half_rn(c[mt][nt][1] + b1v);
                T[cl * 136 + rl + 8]       = __float2half_rn(c[mt][nt][2] + b0v);
                T[(cl + 1) * 136 + rl + 8] = __float2half_rn(c[mt][nt][3] + b1v);
            }
        }
        __syncthreads();
        const int bb = bm >> 10;
        const int kq = bm & 1023;
        for (int f = tid; f < 128 * 16; f += 256) {
            int cl = f >> 4, s8 = f & 15;
            int gc = bnl + cl;
            int hh = gc >> 6, dd = gc & 63;
            size_t o = ((size_t)(bb * NH + hh) * DK + dd) * LSEQ + kq + s8 * 8;
            *(uint4*)(g_Vth + o) = *(const uint4*)&T[cl * 136 + s8 * 8];
        }
    } else {
        __half* dh = (seg == 0) ? g_Qh : g_Kh;
#pragma unroll
        for (int mt = 0; mt < 4; mt++) {
            int row = bm + wm * 64 + mt * 16 + r0;
#pragma unroll
            for (int nt = 0; nt < 4; nt++) {
                int col = bn + wn * 32 + nt * 8 + c0;
                float b0v = bias[col], b1v = bias[col + 1];
                int coll = bnl + wn * 32 + nt * 8 + c0;
                *(uint32_t*)(dh + (size_t)row * DM + coll) =
                    pkh2(__float2half_rn(c[mt][nt][0] + b0v), __float2half_rn(c[mt][nt][1] + b1v));
                *(uint32_t*)(dh + (size_t)(row + 8) * DM + coll) =
                    pkh2(__float2half_rn(c[mt][nt][2] + b0v), __float2half_rn(c[mt][nt][3] + b1v));
            }
        }
    }
}

// ---------------- fp16 single-pass GEMM (3-stage pipe) ----------------
__global__ __launch_bounds__(256, 2) void gemm_fp16(
    const __half* __restrict__ Ah, const __half* __restrict__ Bh,
    const float* __restrict__ bias, float* __restrict__ C,
    __half* __restrict__ Chi, int M, int N, int K, int relu)
{
    extern __shared__ char gsm[];
    const uint32_t base = smem_u32(gsm);

    const int tid = threadIdx.x;
    const int wid = tid >> 5, lane = tid & 31;
    const int wm = wid >> 2, wn = wid & 3;
    const int bm = blockIdx.y * 128, bn = blockIdx.x * 128;

    float c[4][4][4];
#pragma unroll
    for (int mt = 0; mt < 4; mt++)
#pragma unroll
        for (int nt = 0; nt < 4; nt++)
#pragma unroll
            for (int r = 0; r < 4; r++) c[mt][nt][r] = 0.f;

    const int a_m_base = wm * 64 + (lane & 7) + 8 * ((lane >> 3) & 1);
    const int a_kk = 8 * (lane >> 4);
    const int b_n_base = wn * 32 + (lane & 7) + 8 * (lane >> 4);
    const int b_kk = 8 * ((lane >> 3) & 1);

    const int ktiles = K >> 5;

    auto load_tile = [&](int t, int s) {
        const int kbase = t * 32;
        const uint32_t sb = base + s * GSTAGE_S;
#pragma unroll
        for (int i = 0; i < 2; i++) {
            int f = tid + i * 256;
            int row = f >> 2, seg2 = f & 3;
            uint32_t so = (uint32_t)(row * SPAD + seg2 * 8) * 2;
            cp_async16(sb + so, Ah + (size_t)(bm + row) * K + kbase + seg2 * 8);
            cp_async16(sb + 10240 + so, Bh + (size_t)(bn + row) * K + kbase + seg2 * 8);
        }
        cp_commit();
    };

    load_tile(0, 0);
    load_tile(1, 1);
    int ls = 2, cs = 0;
    for (int t = 0; t < ktiles; t++) {
        if (t + 2 < ktiles) {
            load_tile(t + 2, ls);
            if (++ls == 3) ls = 0;
            cp_wait2();
        } else if (t + 1 < ktiles) {
            cp_wait1();
        } else {
            cp_wait0();
        }
        __syncthreads();

        const uint32_t sb = base + cs * GSTAGE_S;
        if (++cs == 3) cs = 0;
        const uint32_t aA = sb, aB = sb + 10240;
#pragma unroll
        for (int kh = 0; kh < 2; kh++) {
            const int k0 = kh * 16;
            uint32_t bh[8];
#pragma unroll
            for (int p = 0; p < 2; p++) {
                uint32_t off = (uint32_t)((b_n_base + p * 16) * SPAD + k0 + b_kk) * 2;
                ldmx4(bh + p * 4, aB + off);
            }
#pragma unroll
            for (int mt = 0; mt < 4; mt++) {
                uint32_t ah[4];
                uint32_t off = (uint32_t)((a_m_base + mt * 16) * SPAD + k0 + a_kk) * 2;
                ldmx4(ah, aA + off);
#pragma unroll
                for (int nt = 0; nt < 4; nt++)
                    mma_f16(c[mt][nt], ah, bh[nt * 2], bh[nt * 2 + 1]);
            }
        }
        __syncthreads();
    }

    const int r0 = lane >> 2, c0 = (lane & 3) * 2;
#pragma unroll
    for (int mt = 0; mt < 4; mt++) {
        int row = bm + wm * 64 + mt * 16 + r0;
#pragma unroll
        for (int nt = 0; nt < 4; nt++) {
            int col = bn + wn * 32 + nt * 8 + c0;
            float b0v = bias[col], b1v = bias[col + 1];
            float v0 = c[mt][nt][0] + b0v, v1 = c[mt][nt][1] + b1v;
            float v2 = c[mt][nt][2] + b0v, v3 = c[mt][nt][3] + b1v;
            if (relu) {
                v0 = fmaxf(v0, 0.f); v1 = fmaxf(v1, 0.f);
                v2 = fmaxf(v2, 0.f); v3 = fmaxf(v3, 0.f);
            }
            if (C) {
                *(float2*)(C + (size_t)row * N + col) = make_float2(v0, v1);
                *(float2*)(C + (size_t)(row + 8) * N + col) = make_float2(v2, v3);
            }
            if (Chi) {
                *(uint32_t*)(Chi + (size_t)row * N + col) =
                    pkh2(__float2half_rn(v0), __float2half_rn(v1));
                *(uint32_t*)(Chi + (size_t)(row + 8) * N + col) =
                    pkh2(__float2half_rn(v2), __float2half_rn(v3));
            }
        }
    }
}

// ---------------- fused flash attention (all fp16 single MMA) ----------------
#define QP 72
#define VP 136
#define OFF_QH 0
#define OFF_KH 18432
#define OFF_VH 36864
#define OFF_WB 54272
#define OFF_SR 71680
#define OFF_F  89088
#define OFF_RKH 89600
#define FLASH_SMEM 96512

__global__ __launch_bounds__(256, 2) void flash_attn(const float* __restrict__ rel_v) {
    extern __shared__ char fsm[];
    float* sWb = (float*)(fsm + OFF_WB);    // [128][34]
    float* sSr = (float*)(fsm + OFF_SR);    // [128][34]
    float* sF  = (float*)(fsm + OFF_F);     // [128]

    const int tid = threadIdx.x;
    const int wid = tid >> 5, lane = tid & 31;
    const int bh = blockIdx.y, b = bh >> 4, h = bh & 15;
    const int bq = blockIdx.x * 128;

    const uint32_t aQ = smem_u32(fsm + OFF_QH);
    const uint32_t aK = smem_u32(fsm + OFF_KH);
    const uint32_t aV = smem_u32(fsm + OFF_VH);
    const uint32_t aRK = smem_u32(fsm + OFF_RKH);

#pragma unroll
    for (int i = 0; i < 4; i++) {
        int f = tid + i * 256;
        int row = f >> 3, seg = f & 7;
        uint32_t so = (uint32_t)(row * QP + seg * 8) * 2;
        cp_async16(aQ + so, g_Qh + (size_t)(b * LSEQ + bq + row) * DM + h * DK + seg * 8);
    }
    for (int f = tid; f < 384; f += 256) {
        int row = f >> 3, seg = f & 7;
        uint32_t so = (uint32_t)(row * QP + seg * 8) * 2;
        cp_async16(aRK + so, g_RKh + row * DK + seg * 8);
    }
    for (int o = tid; o < 128 * 34; o += 256) sWb[o] = 0.f;
    cp_async_wait_all();
    __syncthreads();

    const int a_row = wid * 16 + (lane & 7) + 8 * ((lane >> 3) & 1);
    const int a_kk = 8 * (lane >> 4);
    const int b_row = (lane & 7) + 8 * (lane >> 4);
    const int b_kk = 8 * ((lane >> 3) & 1);
    const int r0 = lane >> 2, c0 = (lane & 3) * 2;
    const int qrow0 = wid * 16 + r0;
    const int q0 = bq + qrow0;

    // ---- sSr = Q . rel_k^T (fp16 single pass) ----
    {
        float csr[6][4];
#pragma unroll
        for (int nt = 0; nt < 6; nt++)
#pragma unroll
            for (int j = 0; j < 4; j++) csr[nt][j] = 0.f;
#pragma unroll
        for (int ks = 0; ks < 4; ks++) {
            uint32_t ah[4];
            ldmx4(ah, aQ + (uint32_t)(a_row * QP + ks * 16 + a_kk) * 2);
            uint32_t rb[12];
#pragma unroll
            for (int p = 0; p < 3; p++)
                ldmx4(rb + p * 4, aRK + (uint32_t)((b_row + p * 16) * QP + ks * 16 + b_kk) * 2);
#pragma unroll
            for (int nt = 0; nt < 6; nt++)
                mma_f16(csr[nt], ah, rb[nt * 2], rb[nt * 2 + 1]);
        }
#pragma unroll
        for (int nt = 0; nt < 6; nt++) {
#pragma unroll
            for (int j = 0; j < 4; j++) {
                int col = nt * 8 + c0 + (j & 1);
                if (col < 34) {
                    int row = (j < 2) ? qrow0 : qrow0 + 8;
                    sSr[row * 34 + col] = csr[nt][j];
                }
            }
        }
        __syncwarp();
    }

    float m0 = -1e30f, m1 = -1e30f, l0 = 0.f, l1 = 0.f;
    float O[8][4];
#pragma unroll
    for (int nt = 0; nt < 8; nt++)
#pragma unroll
        for (int j = 0; j < 4; j++) O[nt][j] = 0.f;

    for (int kt = 0; kt < 8; kt++) {
        const int k0 = kt * 128;
#pragma unroll
        for (int i = 0; i < 4; i++) {
            int f = tid + i * 256;
            int row = f >> 3, seg = f & 7;
            uint32_t so = (uint32_t)(row * QP + seg * 8) * 2;
            cp_async16(aK + so, g_Kh + (size_t)(b * LSEQ + k0 + row) * DM + h * DK + seg * 8);
        }
#pragma unroll
        for (int i = 0; i < 4; i++) {
            int f = tid + i * 256;
            int row = f >> 4, seg = f & 15;
            uint32_t so = (uint32_t)(row * VP + seg * 8) * 2;
            cp_async16(aV + so, g_Vth + ((size_t)bh * DK + row) * LSEQ + k0 + seg * 8);
        }
        cp_async_wait_all();
        __syncthreads();

        float c[16][4];
#pragma unroll
        for (int nt = 0; nt < 16; nt++)
#pragma unroll
            for (int j = 0; j < 4; j++) c[nt][j] = 0.f;

#pragma unroll
        for (int ks = 0; ks < 4; ks++) {
            uint32_t ah[4];
            ldmx4(ah, aQ + (uint32_t)(a_row * QP + ks * 16 + a_kk) * 2);
#pragma unroll
            for (int hh = 0; hh < 2; hh++) {
                uint32_t bhf[16];
#pragma unroll
                for (int p = 0; p < 4; p++)
                    ldmx4(bhf + p * 4,
                          aK + (uint32_t)((b_row + hh * 64 + p * 16) * QP + ks * 16 + b_kk) * 2);
#pragma unroll
                for (int nt = 0; nt < 8; nt++)
                    mma_f16(c[hh * 8 + nt], ah, bhf[nt * 2], bhf[nt * 2 + 1]);
            }
        }

        float tm0 = -1e30f, tm1 = -1e30f;
#pragma unroll
        for (int nt = 0; nt < 16; nt++) {
            int kA = k0 + nt * 8 + c0;
#pragma unroll
            for (int j = 0; j < 4; j++) {
                int kk = kA + (j & 1);
                bool low = (j < 2);
                int q = low ? q0 : q0 + 8;
                int lrow = low ? qrow0 : qrow0 + 8;
                int d = kk - q; d = max(-16, min(16, d));
                float s = (c[nt][j] + sSr[lrow * 34 + d + 16]) * 0.125f;
                c[nt][j] = s;
                if (low) tm0 = fmaxf(tm0, s); else tm1 = fmaxf(tm1, s);
            }
        }
        tm0 = fmaxf(tm0, __shfl_xor_sync(0xffffffffu, tm0, 1));
        tm0 = fmaxf(tm0, __shfl_xor_sync(0xffffffffu, tm0, 2));
        tm1 = fmaxf(tm1, __shfl_xor_sync(0xffffffffu, tm1, 1));
        tm1 = fmaxf(tm1, __shfl_xor_sync(0xffffffffu, tm1, 2));
        float nm0 = fmaxf(m0, tm0), nm1 = fmaxf(m1, tm1);
        float f0 = __expf(m0 - nm0), f1 = __expf(m1 - nm1);
        m0 = nm0; m1 = nm1;
        if ((lane & 3) == 0) { sF[qrow0] = f0; sF[qrow0 + 8] = f1; }
        __syncwarp();
        for (int o = lane; o < 16 * 33; o += 32) {
            int rr = o / 33, cc2 = o % 33;
            sWb[(wid * 16 + rr) * 34 + cc2] *= sF[wid * 16 + rr];
        }
        __syncwarp();

        float sum0 = 0.f, sum1 = 0.f, lo0 = 0.f, lo1 = 0.f, hi0 = 0.f, hi1 = 0.f;
#pragma unroll
        for (int nt = 0; nt < 16; nt++) {
#pragma unroll
            for (int j = 0; j < 4; j++) {
                int kk = k0 + nt * 8 + c0 + (j & 1);
                bool low = (j < 2);
                float p = __expf(c[nt][j] - (low ? nm0 : nm1));
                c[nt][j] = p;
                int q = low ? q0 : q0 + 8;
                int d = kk - q;
                if (low) sum0 += p; else sum1 += p;
                if (d <= -16) { if (low) lo0 += p; else lo1 += p; }
                else if (d >= 16) { if (low) hi0 += p; else hi1 += p; }
                else sWb[(low ? qrow0 : qrow0 + 8) * 34 + d + 16] += p;
            }
        }
        sum0 += __shfl_xor_sync(0xffffffffu, sum0, 1);
        sum0 += __shfl_xor_sync(0xffffffffu, sum0, 2);
        sum1 += __shfl_xor_sync(0xffffffffu, sum1, 1);
        sum1 += __shfl_xor_sync(0xffffffffu, sum1, 2);
        lo0 += __shfl_xor_sync(0xffffffffu, lo0, 1);
        lo0 += __shfl_xor_sync(0xffffffffu, lo0, 2);
        lo1 += __shfl_xor_sync(0xffffffffu, lo1, 1);
        lo1 += __shfl_xor_sync(0xffffffffu, lo1, 2);
        hi0 += __shfl_xor_sync(0xffffffffu, hi0, 1);
        hi0 += __shfl_xor_sync(0xffffffffu, hi0, 2);
        hi1 += __shfl_xor_sync(0xffffffffu, hi1, 1);
        hi1 += __shfl_xor_sync(0xffffffffu, hi1, 2);
        l0 = l0 * f0 + sum0;
        l1 = l1 * f1 + sum1;
        if ((lane & 3) == 0) {
            sWb[qrow0 * 34 + 0] += lo0;  sWb[qrow0 * 34 + 32] += hi0;
            sWb[(qrow0 + 8) * 34 + 0] += lo1;  sWb[(qrow0 + 8) * 34 + 32] += hi1;
        }
#pragma unroll
        for (int nt = 0; nt < 8; nt++) {
            O[nt][0] *= f0; O[nt][1] *= f0; O[nt][2] *= f1; O[nt][3] *= f1;
        }

        // ---- PV: P fp16 single x Vt fp16 single ----
#pragma unroll
        for (int j = 0; j < 8; j++) {
            uint32_t pa[4];
            pa[0] = pkh2(__float2half_rn(c[2 * j][0]), __float2half_rn(c[2 * j][1]));
            pa[1] = pkh2(__float2half_rn(c[2 * j][2]), __float2half_rn(c[2 * j][3]));
            pa[2] = pkh2(__float2half_rn(c[2 * j + 1][0]), __float2half_rn(c[2 * j + 1][1]));
            pa[3] = pkh2(__float2half_rn(c[2 * j + 1][2]), __float2half_rn(c[2 * j + 1][3]));
            uint32_t vh[16];
#pragma unroll
            for (int p = 0; p < 4; p++)
                ldmx4(vh + p * 4, aV + (uint32_t)((b_row + p * 16) * VP + j * 16 + b_kk) * 2);
#pragma unroll
            for (int nt = 0; nt < 8; nt++)
                mma_f16(O[nt], pa, vh[nt * 2], vh[nt * 2 + 1]);
        }
        __syncthreads();
    }

    // ---- epilogue: rank-33 rel_v update, normalize, store fp16 single ----
    float* rv = (float*)(fsm + OFF_KH);
    for (int o = tid; o < NREL * DK; o += 256) rv[o] = rel_v[o];
    __syncthreads();

#pragma unroll 1
    for (int r = 0; r < NREL; r++) {
        float wb0 = sWb[qrow0 * 34 + r];
        float wb1 = sWb[(qrow0 + 8) * 34 + r];
#pragma unroll
        for (int nt = 0; nt < 8; nt++) {
            int d = nt * 8 + c0;
            float rv0 = rv[r * DK + d], rv1 = rv[r * DK + d + 1];
            O[nt][0] += wb0 * rv0; O[nt][1] += wb0 * rv1;
            O[nt][2] += wb1 * rv0; O[nt][3] += wb1 * rv1;
        }
    }
    float inv0 = 1.f / l0, inv1 = 1.f / l1;
    size_t o0 = (size_t)(b * LSEQ + q0) * DM + h * DK;
    size_t o1 = (size_t)(b * LSEQ + q0 + 8) * DM + h * DK;
#pragma unroll
    for (int nt = 0; nt < 8; nt++) {
        int d = nt * 8 + c0;
        *(uint32_t*)(g_Xh + o0 + d) =
            pkh2(__float2half_rn(O[nt][0] * inv0), __float2half_rn(O[nt][1] * inv0));
        *(uint32_t*)(g_Xh + o1 + d) =
            pkh2(__float2half_rn(O[nt][2] * inv1), __float2half_rn(O[nt][3] * inv1));
    }
}

// ---------------- reductions ----------------
__device__ __forceinline__ float block_sum(float v, float* red) {
    int lane = threadIdx.x & 31, w = threadIdx.x >> 5;
#pragma unroll
    for (int o = 16; o; o >>= 1) v += __shfl_xor_sync(0xffffffffu, v, o);
    if (lane == 0) red[w] = v;
    __syncthreads();
    if (w == 0) {
        float t = (lane < 8) ? red[lane] : 0.f;
#pragma unroll
        for (int o = 4; o; o >>= 1) t += __shfl_xor_sync(0xffffffffu, t, o);
        if (lane == 0) red[0] = t;
    }
    __syncthreads();
    float r = red[0];
    __syncthreads();
    return r;
}

// ---------------- layernorm (optional fp16 single output) ----------------
__global__ void layernorm_k(const float* __restrict__ X, const float* __restrict__ Res,
                            const float* __restrict__ gam, const float* __restrict__ bet,
                            float* __restrict__ O, __half* __restrict__ Oh) {
    int row = blockIdx.x, tid = threadIdx.x;
    __shared__ float red[32];
    float4 v = *(const float4*)(X + (size_t)row * DM + tid * 4);
    if (Res) {
        float4 rr = *(const float4*)(Res + (size_t)row * DM + tid * 4);
        v.x += rr.x; v.y += rr.y; v.z += rr.z; v.w += rr.w;
    }
    float s = block_sum(v.x + v.y + v.z + v.w, red);
    float s2 = block_sum(v.x * v.x + v.y * v.y + v.z * v.z + v.w * v.w, red);
    float mu = s * (1.f / DM);
    float var = s2 * (1.f / DM) - mu * mu;
    float rstd = rsqrtf(var + 1e-6f);
    float4 g4 = *(const float4*)(gam + tid * 4);
    float4 b4 = *(const float4*)(bet + tid * 4);
    float4 o;
    o.x = (v.x - mu) * rstd * g4.x + b4.x;
    o.y = (v.y - mu) * rstd * g4.y + b4.y;
    o.z = (v.z - mu) * rstd * g4.z + b4.z;
    o.w = (v.w - mu) * rstd * g4.w + b4.w;
    if (O) *(float4*)(O + (size_t)row * DM + tid * 4) = o;
    if (Oh) {
        uint2 ph = make_uint2(pkh2(__float2half_rn(o.x), __float2half_rn(o.y)),
                              pkh2(__float2half_rn(o.z), __float2half_rn(o.w)));
        *(uint2*)(Oh + (size_t)row * DM + tid * 4) = ph;
    }
}

// ---------------- launch ----------------
static void* sym_addr(const void* s) { void* p = nullptr; cudaGetSymbolAddress(&p, s); return p; }

extern "C" void kernel_launch(void* const* d_in, const int* in_sizes, int n_in,
                              void* d_out, int out_size) {
    const float* q    = (const float*)d_in[0];
    const float* k    = (const float*)d_in[1];
    const float* v    = (const float*)d_in[2];
    const float* wq   = (const float*)d_in[3];
    const float* bq   = (const float*)d_in[4];
    const float* wk   = (const float*)d_in[5];
    const float* bk   = (const float*)d_in[6];
    const float* wv   = (const float*)d_in[7];
    const float* bv   = (const float*)d_in[8];
    const float* wfc  = (const float*)d_in[9];
    const float* bfc  = (const float*)d_in[10];
    const float* w1   = (const float*)d_in[11];
    const float* b1   = (const float*)d_in[12];
    const float* w2   = (const float*)d_in[13];
    const float* b2   = (const float*)d_in[14];
    const float* ln_g = (const float*)d_in[15];
    const float* ln_b = (const float*)d_in[16];
    const float* relk = (const float*)d_in[17];
    const float* relv = (const float*)d_in[18];
    float* out = (float*)d_out;

    float* pTmp  = (float*)sym_addr(g_tmp);
    float* pLn1  = (float*)sym_addr(g_ln1);
    float* pT2   = (float*)sym_addr(g_t2);
    float* pBqkv = (float*)sym_addr(g_bqkv);
    __half* pAh  = (__half*)sym_addr(g_Ah);
    __half* pXh  = (__half*)sym_addr(g_Xh);
    __half* pWh  = (__half*)sym_addr(g_Wh);

    cudaFuncSetAttribute(gemm_qkv_h, cudaFuncAttributeMaxDynamicSharedMemorySize, GEMM_S_SMEM);
    cudaFuncSetAttribute(gemm_fp16, cudaFuncAttributeMaxDynamicSharedMemorySize, GEMM_S_SMEM);
    cudaFuncSetAttribute(flash_attn, cudaFuncAttributeMaxDynamicSharedMemorySize, FLASH_SMEM);

    const int nD4 = ROWS * DM / 4 / 256;
    dim3 tBlk(256);
    dim3 tGridQKV(DM / 64, DM / 64, 3);
    dim3 tGridD(DM / 64, DM / 64);
    dim3 tGridW1(DI / 64, DM / 64);
    dim3 tGridW2(DM / 64, DI / 64);
    dim3 gD(DM / 128, ROWS / 128);
    dim3 gI(DI / 128, ROWS / 128);
    dim3 gQKV(3 * DM / 128, ROWS / 128);
    dim3 gC3(nD4, 3);

    // ---- merged QKV (fp16 single-pass): stacked weights + inputs, fused V-transpose ----
    bias_concat<<<12, 256>>>(bq, bk, bv);
    relk_h<<<12, 256>>>(relk);
    convT3_h<<<tGridQKV, tBlk>>>(wq, wk, wv, pWh);
    conv3_h<<<gC3, 256>>>(q, k, v, pAh);
    gemm_qkv_h<<<gQKV, 256, GEMM_S_SMEM>>>(pAh, pWh, pBqkv);

    // fused flash attention -> attn fp16 into g_Xh
    dim3 gfa(LSEQ / 128, BHN);
    flash_attn<<<gfa, 256, FLASH_SMEM>>>(relv);

    // out-proj + LN1 (emits fp16 for FFN1)
    conv_T_h<<<tGridD, tBlk>>>(wfc, pWh, DM, DM);
    gemm_fp16<<<gD, 256, GEMM_S_SMEM>>>(pXh, pWh, bfc, pTmp, nullptr, ROWS, DM, DM, 0);
    layernorm_k<<<ROWS, 256>>>(pTmp, q, ln_g, ln_b, pLn1, pXh);

    // FFN
    conv_T_h<<<tGridW1, tBlk>>>(w1, pWh, DM, DI);
    gemm_fp16<<<gI, 256, GEMM_S_SMEM>>>(pXh, pWh, b1, nullptr, pAh, ROWS, DI, DM, 1);

    conv_T_h<<<tGridW2, tBlk>>>(w2, pWh, DI, DM);
    gemm_fp16<<<gD, 256, GEMM_S_SMEM>>>(pAh, pWh, b2, pT2, nullptr, ROWS, DM, DI, 0);
    layernorm_k<<<ROWS, 256>>>(pT2, pLn1, ln_g, ln_b, out, nullptr);
}